// round 2
// baseline (speedup 1.0000x reference)
#include <cuda_runtime.h>
#include <stdint.h>

#define BATCH 1024
#define KSEL  64
#define IFEAT 4096
#define OFEAT 4096

// Device scratch (static device globals are allowed; no runtime alloc).
__device__ float g_WT[(size_t)IFEAT * OFEAT];   // 64 MB, W transposed: WT[c][o]
__device__ float g_y[(size_t)BATCH * OFEAT];    // 16 MB, dense pre-topk result

// ---------------------------------------------------------------------------
// Transpose W (O,I) -> WT (I,O). 32x32 smem tiles, coalesced both ways.
// ---------------------------------------------------------------------------
__global__ void transpose_kernel(const float* __restrict__ W)
{
    __shared__ float t[32][33];
    const int bc = blockIdx.x * 32;   // column of W (input-feature dim)
    const int br = blockIdx.y * 32;   // row of W (output-feature dim)
    const int x = threadIdx.x;        // 0..31
    const int y = threadIdx.y;        // 0..7
#pragma unroll
    for (int i = 0; i < 32; i += 8)
        t[y + i][x] = W[(size_t)(br + y + i) * IFEAT + bc + x];
    __syncthreads();
#pragma unroll
    for (int i = 0; i < 32; i += 8)
        g_WT[(size_t)(bc + y + i) * OFEAT + br + x] = t[x][y + i];
}

// ---------------------------------------------------------------------------
// Batched sparse gemv: y[b,o] = sum_{k=0..63} x[b,k] * WT[idx[b,k]][o] + bias[o]
// Strict sequential-k FMA chain per output (matches reference einsum rounding),
// bias added once at the end (matches `einsum + bias`).
// Block: 256 threads, covers 512 outputs (2 per thread). Grid: (8, BATCH).
// All WT loads are fully coalesced 128B lines; WT is L2-resident (64MB < 126MB).
// ---------------------------------------------------------------------------
__global__ void gemv_kernel(const float* __restrict__ x,
                            const int*   __restrict__ idx,
                            const float* __restrict__ bias)
{
    __shared__ float sx[KSEL];
    __shared__ int   soff[KSEL];

    const int b = blockIdx.y;
    const int o = blockIdx.x * 512 + threadIdx.x;

    if (threadIdx.x < KSEL) {
        sx[threadIdx.x]   = x[b * KSEL + threadIdx.x];
        soff[threadIdx.x] = idx[b * KSEL + threadIdx.x] * OFEAT;
    }
    __syncthreads();

    float a0 = 0.f, a1 = 0.f;
#pragma unroll 8
    for (int k = 0; k < KSEL; ++k) {
        const float xv = sx[k];
        const float* p = g_WT + soff[k] + o;
        a0 = fmaf(xv, p[0],   a0);
        a1 = fmaf(xv, p[256], a1);
    }
    g_y[(size_t)b * OFEAT + o]       = a0 + bias[o];
    g_y[(size_t)b * OFEAT + o + 256] = a1 + bias[o + 256];
}

// ---------------------------------------------------------------------------
// Exact top-64 per sample: monotone uint keys, 4-pass radix select of the
// exact rank-64 key, collect >=T, bitonic sort with composite key
// (value desc, index asc) == jax.lax.top_k stable semantics. Deterministic.
// ---------------------------------------------------------------------------
__device__ __forceinline__ unsigned f2u(float f) {
    unsigned u = __float_as_uint(f);
    return (u & 0x80000000u) ? ~u : (u | 0x80000000u);
}
__device__ __forceinline__ float u2f(unsigned u) {
    unsigned b = (u & 0x80000000u) ? (u ^ 0x80000000u) : ~u;
    return __uint_as_float(b);
}

__global__ void topk_kernel(float* __restrict__ out, int out_size)
{
    __shared__ unsigned su[OFEAT];
    __shared__ unsigned hist[256];
    __shared__ unsigned long long cand[256];
    __shared__ unsigned sh_prefix;
    __shared__ int sh_need;
    __shared__ int ncand;

    const int b = blockIdx.x;
    const int tid = threadIdx.x;

    for (int o = tid; o < OFEAT; o += blockDim.x)
        su[o] = f2u(g_y[(size_t)b * OFEAT + o]);

    // Radix-select exact rank-64 key T (descending).
    unsigned prefix = 0, mask = 0;
    int shift = 24, need = KSEL;
    for (int pass = 0; pass < 4; ++pass) {
        hist[tid] = 0;
        __syncthreads();
        for (int o = tid; o < OFEAT; o += blockDim.x) {
            unsigned u = su[o];
            if ((u & mask) == prefix)
                atomicAdd(&hist[(u >> shift) & 255], 1u);
        }
        __syncthreads();
        if (tid == 0) {
            int cum = 0;
            for (int bin = 255; bin >= 0; --bin) {
                cum += (int)hist[bin];
                if (cum >= need) {
                    sh_prefix = prefix | ((unsigned)bin << shift);
                    sh_need   = need - (cum - (int)hist[bin]);
                    break;
                }
            }
        }
        __syncthreads();
        prefix = sh_prefix;
        need   = sh_need;
        mask  |= (0xFFu << shift);
        shift -= 8;
    }
    const unsigned T = prefix;

    // Collect all u >= T (>= 64; ties beyond 256 impossible with these inputs).
    if (tid == 0) ncand = 0;
    cand[tid] = 0ull;
    __syncthreads();
    for (int o = tid; o < OFEAT; o += blockDim.x) {
        unsigned u = su[o];
        if (u >= T) {
            int p = atomicAdd(&ncand, 1);
            if (p < 256)
                cand[p] = ((unsigned long long)u << 32) | (unsigned)(4095 - o);
        }
    }
    __syncthreads();

    // Bitonic sort 256 keys descending (value desc, index asc on ties).
    for (int k2 = 2; k2 <= 256; k2 <<= 1) {
        for (int j2 = k2 >> 1; j2 > 0; j2 >>= 1) {
            int i = tid, ixj = tid ^ j2;
            if (ixj > i) {
                bool desc = ((i & k2) == 0);
                unsigned long long a = cand[i], bb = cand[ixj];
                if (desc ? (a < bb) : (a > bb)) { cand[i] = bb; cand[ixj] = a; }
            }
            __syncthreads();
        }
    }

    if (tid < KSEL) {
        unsigned long long key = cand[tid];
        unsigned u = (unsigned)(key >> 32);
        int o = 4095 - (int)(key & 0xFFFFFFFFull);
        int half = out_size >> 1;
        out[(size_t)b * KSEL + tid]        = u2f(u);
        out[(size_t)half + b * KSEL + tid] = (float)o;
    }
}

// ---------------------------------------------------------------------------
extern "C" void kernel_launch(void* const* d_in, const int* in_sizes, int n_in,
                              void* d_out, int out_size)
{
    const float* input  = nullptr;
    const float* weight = nullptr;
    const float* bias   = nullptr;
    const int*   idx    = nullptr;
    for (int i = 0; i < n_in; ++i) {
        if (in_sizes[i] == OFEAT * IFEAT)      weight = (const float*)d_in[i];
        else if (in_sizes[i] == OFEAT)         bias   = (const float*)d_in[i];
        else if (in_sizes[i] == BATCH * KSEL) {
            if (!input) input = (const float*)d_in[i];
            else        idx   = (const int*)d_in[i];
        }
    }

    transpose_kernel<<<dim3(IFEAT / 32, OFEAT / 32), dim3(32, 8)>>>(weight);
    gemv_kernel<<<dim3(OFEAT / 512, BATCH), 256>>>(input, idx, bias);
    topk_kernel<<<BATCH, 256>>>((float*)d_out, out_size);
}